// round 8
// baseline (speedup 1.0000x reference)
#include <cuda_runtime.h>
#include <cstddef>

// Problem constants
#define BB   128
#define TT   1024
#define II   256
#define HH   512
#define CLIPV 5.0f

// Tiling: 32 j-tiles x 4 m-blocks = 128 persistent blocks, 384 threads each.
// K=768 split into 3 groups of 256: grp0=h[0:256], grp1=h[256:512], grp2=x[0:256].
#define JT    16         // j columns per block
#define MB    32         // batch rows per block
#define NITER 8          // 8 chunks of K=32 per group

// Device scratch (no cudaMalloc allowed)
__device__ float g_h[2][BB * HH];
__device__ unsigned g_arrive;
__device__ unsigned g_release;

typedef unsigned long long u64;

__device__ __forceinline__ u64 ffma2(u64 a, u64 b, u64 c) {
    u64 d;
    asm("fma.rn.f32x2 %0, %1, %2, %3;" : "=l"(d) : "l"(a), "l"(b), "l"(c));
    return d;
}
__device__ __forceinline__ float sigm(float v) { return 1.0f / (1.0f + __expf(-v)); }

// Dynamic smem layout (floats):
//   Wsm : [3 gates][768 k][16 cols]                 = 36864 fl (147456 B)
//   As2 : float2 [(2 buf x 3 grp)*32 kk][32 cols]   =  6144 f2 ( 49152 B)
//   part: [3 arrays R/Z/N][3 grp][512 cells]        =  4608 fl ( 18432 B)
#define W_FLOATS    (3 * 768 * 16)
#define AS_F2       (2 * 3 * 32 * 32)
#define PART_FLOATS (3 * 3 * 512)
#define SMEM_BYTES  (W_FLOATS * 4 + AS_F2 * 8 + PART_FLOATS * 4)

__global__ void __launch_bounds__(384, 1)
gru_persistent(const float* __restrict__ x,      // [B, T, I]
               const float* __restrict__ w_ih,   // [3H, I]
               const float* __restrict__ w_hh,   // [3H, H]
               const float* __restrict__ b_ih,   // [3H]
               const float* __restrict__ b_hh,   // [3H]
               float* __restrict__ out,          // [B, T, H] (+ [B,H] tail)
               int write_hlast)
{
    extern __shared__ float smem[];
    float*  Wsm  = smem;                              // resident weight slice
    float2* As2  = (float2*)(smem + W_FLOATS);        // A tiles, value-duplicated, pair-swizzled
    float*  partR = smem + W_FLOATS + AS_F2 * 2;      // [3][512]
    float*  partZ = partR + 3 * 512;
    float*  partN = partZ + 3 * 512;                  // grp0,1 = Nh ; grp2 = Ni

    // [0]=r bias (b_ih+b_hh), [1]=z bias, [2]=n h-bias (b_hh), [3]=n x-bias (b_ih)
    __shared__ float bias_sm[4][JT];

    const int tid = threadIdx.x;
    const int j0  = blockIdx.x * JT;
    const int m0  = blockIdx.y * MB;
    const unsigned nblocks = gridDim.x * gridDim.y;

    if (tid < JT) {
        const int j = j0 + tid;
        bias_sm[0][tid] = b_ih[j] + b_hh[j];
        bias_sm[1][tid] = b_ih[HH + j] + b_hh[HH + j];
        bias_sm[2][tid] = b_hh[2 * HH + j];
        bias_sm[3][tid] = b_ih[2 * HH + j];
    }

    // One-time: weight slice into smem. Wsm[(g*768 + k)*16 + c]; k<512 h, k>=512 x.
    for (int gc = 0; gc < 48; gc++) {
        const int g = gc >> 4, c = gc & 15;
        const int col = g * HH + j0 + c;
        const float* __restrict__ srcH = w_hh + (size_t)col * HH;
        const float* __restrict__ srcI = w_ih + (size_t)col * II;
        for (int k = tid; k < 768; k += 384) {
            float v = (k < HH) ? srcH[k] : srcI[k - HH];
            Wsm[(g * 768 + k) * 16 + c] = v;
        }
    }
    __syncthreads();

    // Thread roles: grp = tid/128 selects K third; within group:
    //   jp = j-pair (cols j0+2jp, j0+2jp+1), rg = row-pair (rows 2rg, 2rg+1)
    const int grp = tid >> 7;       // 0..2
    const int t7  = tid & 127;
    const int jp  = t7 & 7;
    const int rg  = t7 >> 3;        // 0..15

    float ra[8];                    // staging: 3*32*32 = 3072 floats / 384 thr

    for (int t = 0; t < TT; t++) {
        const float* __restrict__ hprev = g_h[t & 1];
        float* __restrict__       hnext = g_h[(t + 1) & 1];

        u64 aR0 = 0, aR1 = 0, aZ0 = 0, aZ1 = 0, aN0 = 0, aN1 = 0;

        // --- staging: every thread loads 8 elements covering all 3 groups' tiles.
        #define STAGE_LOAD(ITER)                                                   \
        {   const int _i = (ITER);                                                 \
            _Pragma("unroll")                                                      \
            for (int u = 0; u < 8; u++) {                                          \
                int idx = tid + u * 384;                                           \
                int g2  = idx >> 10;                                               \
                int rem = idx & 1023;                                              \
                int kk  = rem & 31;                                                \
                int m   = rem >> 5;                                                \
                int ch  = g2 * 8 + _i;                                             \
                float v;                                                           \
                if (ch < 16) v = hprev[(m0 + m) * HH + ch * 32 + kk];              \
                else v = x[((size_t)(m0 + m) * TT + t) * II + (ch - 16) * 32 + kk];\
                ra[u] = v;                                                         \
            } }
        // Pair-swizzle: row m -> pair p=m>>1, lo=m&1; column f2 index
        // 2*((p+kk)&15)+lo. Keeps the (2rg,2rg+1) pair contiguous for LDS.128.
        #define STAGE_STORE(BUF)                                                   \
        {   const int _b = (BUF);                                                  \
            _Pragma("unroll")                                                      \
            for (int u = 0; u < 8; u++) {                                          \
                int idx = tid + u * 384;                                           \
                int g2  = idx >> 10;                                               \
                int rem = idx & 1023;                                              \
                int kk  = rem & 31;                                                \
                int m   = rem >> 5;                                                \
                int p   = m >> 1, lo = m & 1;                                      \
                int col = 2 * (((p + kk) & 15)) + lo;                              \
                As2[((_b * 3 + g2) * 32 + kk) * 32 + col] = make_float2(ra[u], ra[u]); \
            } }
        // Inner K-loop: 3 LDS.64 (W) + 1 LDS.128 (A pair) + 6 FFMA2 per k.
        #define KLOOP(K0, TBASE)                                                   \
            _Pragma("unroll")                                                      \
            for (int kk = 0; kk < 32; kk++) {                                      \
                const u64 wr = *(const u64*)(Wsm + (0*768 + (K0)+kk)*16 + 2*jp);   \
                const u64 wz = *(const u64*)(Wsm + (1*768 + (K0)+kk)*16 + 2*jp);   \
                const u64 wn = *(const u64*)(Wsm + (2*768 + (K0)+kk)*16 + 2*jp);   \
                const float2* arow = As2 + ((TBASE) + kk) * 32;                    \
                const u64* ap = (const u64*)(arow + 2 * ((rg + kk) & 15));         \
                u64 a0 = ap[0], a1 = ap[1];                                        \
                aR0 = ffma2(a0, wr, aR0);  aR1 = ffma2(a1, wr, aR1);               \
                aZ0 = ffma2(a0, wz, aZ0);  aZ1 = ffma2(a1, wz, aZ1);               \
                aN0 = ffma2(a0, wn, aN0);  aN1 = ffma2(a1, wn, aN1);               \
            }

        STAGE_LOAD(0);
        STAGE_STORE(0);
        __syncthreads();

        for (int i = 0; i < NITER; i++) {
            if (i + 1 < NITER) STAGE_LOAD(i + 1);
            {
                const int buf   = i & 1;
                const int chunk = grp * 8 + i;        // grp0:0..7 grp1:8..15 grp2:16..23
                const int k0    = chunk * 32;         // Wsm k coordinate
                const int tbase = (buf * 3 + grp) * 32;
                KLOOP(k0, tbase);
            }
            if (i + 1 < NITER) STAGE_STORE((i + 1) & 1);
            __syncthreads();
        }

        // --- write partials: cell = m*16 + jj; aX0 = row 2rg, aX1 = row 2rg+1.
        {
            const int c0 = (2 * rg) * 16 + 2 * jp;
            const int c1 = c0 + 16;
            *(u64*)&partR[grp * 512 + c0] = aR0;  *(u64*)&partR[grp * 512 + c1] = aR1;
            *(u64*)&partZ[grp * 512 + c0] = aZ0;  *(u64*)&partZ[grp * 512 + c1] = aZ1;
            *(u64*)&partN[grp * 512 + c0] = aN0;  *(u64*)&partN[grp * 512 + c1] = aN1;
        }
        __syncthreads();

        // --- epilogue: gates + state update.
        for (int cell = tid; cell < 512; cell += 384) {
            int m = cell >> 4, jj = cell & 15;
            int b = m0 + m, j = j0 + jj;
            float rsum = partR[cell] + partR[512 + cell] + partR[1024 + cell]
                       + bias_sm[0][jj];
            float zsum = partZ[cell] + partZ[512 + cell] + partZ[1024 + cell]
                       + bias_sm[1][jj];
            float nh   = partN[cell] + partN[512 + cell] + bias_sm[2][jj];
            float ni   = partN[1024 + cell] + bias_sm[3][jj];
            float r_ = sigm(rsum);
            float z_ = sigm(zsum);
            float n_ = tanhf(ni + r_ * nh);
            float hold = hprev[b * HH + j];
            float hn = (1.0f - z_) * n_ + z_ * hold;
            hn = fminf(CLIPV, fmaxf(-CLIPV, hn));
            hnext[b * HH + j] = hn;
            out[((size_t)b * TT + t) * HH + j] = hn;
            if (write_hlast && t == TT - 1)
                out[(size_t)BB * TT * HH + b * HH + j] = hn;
        }

        // --- grid barrier (128 co-resident blocks; 1 block/SM by smem) ---
        __syncthreads();
        if (tid == 0) {
            __threadfence();
            unsigned prev = atomicAdd(&g_arrive, 1u);
            unsigned target = (unsigned)(t + 1) * nblocks;
            if (prev + 1u == target) {
                atomicExch(&g_release, (unsigned)(t + 1));
            } else {
                while (*(volatile unsigned*)&g_release < (unsigned)(t + 1))
                    __nanosleep(32);
            }
            __threadfence();
        }
        __syncthreads();

        #undef STAGE_LOAD
        #undef STAGE_STORE
        #undef KLOOP
    }
}

// Init: tile h0 [1,H] -> g_h[0] as [B,H]; reset barrier counters.
__global__ void init_h(const float* __restrict__ h0) {
    int i = blockIdx.x * 256 + threadIdx.x;
    if (i < BB * HH) g_h[0][i] = h0[i & (HH - 1)];
    if (i == 0) { g_arrive = 0u; g_release = 0u; }
}

extern "C" void kernel_launch(void* const* d_in, const int* in_sizes, int n_in,
                              void* d_out, int out_size) {
    const float* x    = (const float*)d_in[0];
    const float* h0   = (const float*)d_in[1];
    const float* w_ih = (const float*)d_in[2];
    const float* w_hh = (const float*)d_in[3];
    const float* b_ih = (const float*)d_in[4];
    const float* b_hh = (const float*)d_in[5];
    float* out = (float*)d_out;

    cudaFuncSetAttribute(gru_persistent,
                         cudaFuncAttributeMaxDynamicSharedMemorySize, SMEM_BYTES);

    init_h<<<(BB * HH + 255) / 256, 256>>>(h0);

    const size_t main_elems = (size_t)BB * TT * HH;
    int write_hlast = ((size_t)out_size >= main_elems + (size_t)BB * HH) ? 1 : 0;

    dim3 grid(HH / JT, BB / MB);   // 32 x 4 = 128 blocks, 1 per SM
    gru_persistent<<<grid, 384, SMEM_BYTES>>>(x, w_ih, w_hh, b_ih, b_hh, out,
                                              write_hlast);
}

// round 9
// speedup vs baseline: 1.2321x; 1.2321x over previous
#include <cuda_runtime.h>
#include <cstddef>

// Problem constants
#define BB   128
#define TT   1024
#define II   256
#define HH   512
#define CLIPV 5.0f

// 32 j-tiles x 4 m-blocks = 128 persistent blocks, 384 threads (12 warps).
// K=768 in 3 slices of 256: s0=h[0:256], s1=h[256:512], s2=x[0:256].
// Warp w: kslice = w>>2 (0..2), msub = w&3 (8 rows each).
// Lane l: ksub = l>>4, colgrp = (l>>2)&3, rr = l&3.
// Thread tile: rows {msub*8+rr*2, +1} x cols {colgrp*4..+3} x 3 gates.
#define JT    16
#define MB    32
#define NITER 8          // 8 chunks of K=32 per slice

__device__ float g_h[2][BB * HH];
__device__ unsigned g_arrive;
__device__ unsigned g_release;

typedef unsigned long long u64;

__device__ __forceinline__ u64 ffma2(u64 a, u64 b, u64 c) {
    u64 d;
    asm("fma.rn.f32x2 %0, %1, %2, %3;" : "=l"(d) : "l"(a), "l"(b), "l"(c));
    return d;
}
__device__ __forceinline__ float sigm(float v) { return 1.0f / (1.0f + __expf(-v)); }

// Dynamic smem (floats):
//   Wsm : [3 gates][768 k][16 cols] natural        = 36864 fl (147456 B)
//   As2 : float2 [(2 buf x 3 slice)*32 kk][32 m']  =  6144 f2 ( 49152 B)
//   part: [R,Z,N][3 slice][512 cells]              =  4608 fl ( 18432 B)
#define W_FLOATS    (3 * 768 * 16)
#define AS_F2       (2 * 3 * 32 * 32)
#define PART_FLOATS (3 * 3 * 512)
#define SMEM_BYTES  (W_FLOATS * 4 + AS_F2 * 8 + PART_FLOATS * 4)

__global__ void __launch_bounds__(384, 1)
gru_persistent(const float* __restrict__ x,      // [B, T, I]
               const float* __restrict__ w_ih,   // [3H, I]
               const float* __restrict__ w_hh,   // [3H, H]
               const float* __restrict__ b_ih,   // [3H]
               const float* __restrict__ b_hh,   // [3H]
               float* __restrict__ out,          // [B, T, H] (+ [B,H] tail)
               int write_hlast)
{
    extern __shared__ float smem[];
    float*  Wsm   = smem;
    float2* As2   = (float2*)(smem + W_FLOATS);
    float*  partR = smem + W_FLOATS + AS_F2 * 2;
    float*  partZ = partR + 3 * 512;
    float*  partN = partZ + 3 * 512;              // s0,s1 = Nh ; s2 = Ni

    __shared__ float bias_sm[4][JT];

    const int tid = threadIdx.x;
    const int j0  = blockIdx.x * JT;
    const int m0  = blockIdx.y * MB;
    const unsigned nblocks = gridDim.x * gridDim.y;

    if (tid < JT) {
        const int j = j0 + tid;
        bias_sm[0][tid] = b_ih[j] + b_hh[j];
        bias_sm[1][tid] = b_ih[HH + j] + b_hh[HH + j];
        bias_sm[2][tid] = b_hh[2 * HH + j];
        bias_sm[3][tid] = b_ih[2 * HH + j];
    }

    // Weight slice into smem, natural layout (NO duplication).
    for (int gc = 0; gc < 48; gc++) {
        const int g = gc >> 4, c = gc & 15;
        const int col = g * HH + j0 + c;
        const float* __restrict__ srcH = w_hh + (size_t)col * HH;
        const float* __restrict__ srcI = w_ih + (size_t)col * II;
        for (int k = tid; k < 768; k += 384) {
            float v = (k < HH) ? srcH[k] : srcI[k - HH];
            Wsm[(g * 768 + k) * 16 + c] = v;
        }
    }
    __syncthreads();

    const int w       = tid >> 5;
    const int kslice  = w >> 2;          // 0..2
    const int msub    = w & 3;           // 0..3
    const int l       = tid & 31;
    const int ksub    = l >> 4;          // 0..1
    const int colgrp  = (l >> 2) & 3;    // 0..3
    const int rr      = l & 3;           // 0..3
    const int r0      = msub * 8 + rr * 2;   // even row base (rows r0, r0+1)

    float ra[8];

    for (int t = 0; t < TT; t++) {
        const float* __restrict__ hprev = g_h[t & 1];
        float* __restrict__       hnext = g_h[(t + 1) & 1];

        // acc[gate][row 0/1][colpair 0/1]
        u64 acc[3][2][2];
        #pragma unroll
        for (int g = 0; g < 3; g++)
            #pragma unroll
            for (int a = 0; a < 2; a++)
                #pragma unroll
                for (int b = 0; b < 2; b++) acc[g][a][b] = 0;

        // --- staging loads (gmem, coalesced: lanes sweep kk) ---
        #define STAGE_LOAD(ITER)                                                   \
        {   const int _i = (ITER);                                                 \
            _Pragma("unroll")                                                      \
            for (int u = 0; u < 8; u++) {                                          \
                int idx = tid + u * 384;                                           \
                int s2  = idx >> 10;                                               \
                int rem = idx & 1023;                                              \
                int kk  = rem & 31;                                                \
                int m   = rem >> 5;                                                \
                int ch  = s2 * 8 + _i;                                             \
                float v;                                                           \
                if (ch < 16) v = hprev[(m0 + m) * HH + ch * 32 + kk];              \
                else v = x[((size_t)(m0 + m) * TT + t) * II + (ch - 16) * 32 + kk];\
                ra[u] = v;                                                         \
            } }
        // Store duplicated (v,v) with even-rotation swizzle: m' = (m + 2kk) & 31.
        // Keeps row pairs adjacent and 16B-aligned for the KLOOP LDS.128.
        #define STAGE_STORE(BUF)                                                   \
        {   const int _b = (BUF);                                                  \
            _Pragma("unroll")                                                      \
            for (int u = 0; u < 8; u++) {                                          \
                int idx = tid + u * 384;                                           \
                int s2  = idx >> 10;                                               \
                int rem = idx & 1023;                                              \
                int kk  = rem & 31;                                                \
                int m   = rem >> 5;                                                \
                int mr  = (m + 2 * kk) & 31;                                       \
                As2[((_b * 3 + s2) * 32 + kk) * 32 + mr] = make_float2(ra[u], ra[u]); \
            } }
        // Inner loop: per k: 1 LDS.128 (A dup row-pair) + 3 LDS.128 (W, 4 cols/gate)
        // + 12 FFMA2. ksub lanes interleave even/odd k.
        #define KLOOP(KBASE, TBASE)                                                \
            _Pragma("unroll")                                                      \
            for (int i2 = 0; i2 < 16; i2++) {                                      \
                const int kk = 2 * i2 + ksub;                                      \
                const int mr = (r0 + 2 * kk) & 31;                                 \
                const ulonglong2 av = *(const ulonglong2*)(As2 + ((TBASE) + kk) * 32 + mr); \
                const u64 a0 = av.x, a1 = av.y;                                    \
                _Pragma("unroll")                                                  \
                for (int g = 0; g < 3; g++) {                                      \
                    const ulonglong2 wv = *(const ulonglong2*)                     \
                        (Wsm + (g * 768 + (KBASE) + kk) * 16 + colgrp * 4);        \
                    acc[g][0][0] = ffma2(a0, wv.x, acc[g][0][0]);                  \
                    acc[g][0][1] = ffma2(a0, wv.y, acc[g][0][1]);                  \
                    acc[g][1][0] = ffma2(a1, wv.x, acc[g][1][0]);                  \
                    acc[g][1][1] = ffma2(a1, wv.y, acc[g][1][1]);                  \
                }                                                                  \
            }

        STAGE_LOAD(0);
        STAGE_STORE(0);
        __syncthreads();

        for (int i = 0; i < NITER; i++) {
            if (i + 1 < NITER) STAGE_LOAD(i + 1);
            {
                const int buf   = i & 1;
                const int kbase = kslice * 256 + i * 32;       // Wsm k coordinate
                const int tbase = (buf * 3 + kslice) * 32;     // As2 row base
                KLOOP(kbase, tbase);
            }
            if (i + 1 < NITER) STAGE_STORE((i + 1) & 1);
            __syncthreads();
        }

        // --- merge ksub halves (xor-shuffle over lane bit 16), then write partials.
        {
            #pragma unroll
            for (int g = 0; g < 3; g++)
                #pragma unroll
                for (int a = 0; a < 2; a++)
                    #pragma unroll
                    for (int b = 0; b < 2; b++) {
                        float2 v = *(float2*)&acc[g][a][b];
                        v.x += __shfl_xor_sync(0xffffffffu, v.x, 16);
                        v.y += __shfl_xor_sync(0xffffffffu, v.y, 16);
                        acc[g][a][b] = *(u64*)&v;
                    }
            if (ksub == 0) {
                #pragma unroll
                for (int a = 0; a < 2; a++) {
                    const int cell = (r0 + a) * 16 + colgrp * 4;
                    #pragma unroll
                    for (int b = 0; b < 2; b++) {
                        *(u64*)&partR[kslice * 512 + cell + 2 * b] = acc[0][a][b];
                        *(u64*)&partZ[kslice * 512 + cell + 2 * b] = acc[1][a][b];
                        *(u64*)&partN[kslice * 512 + cell + 2 * b] = acc[2][a][b];
                    }
                }
            }
        }
        __syncthreads();

        // --- epilogue: gates + state update.
        for (int cell = tid; cell < 512; cell += 384) {
            int m = cell >> 4, jj = cell & 15;
            int b = m0 + m, j = j0 + jj;
            float rsum = partR[cell] + partR[512 + cell] + partR[1024 + cell]
                       + bias_sm[0][jj];
            float zsum = partZ[cell] + partZ[512 + cell] + partZ[1024 + cell]
                       + bias_sm[1][jj];
            float nh   = partN[cell] + partN[512 + cell] + bias_sm[2][jj];
            float ni   = partN[1024 + cell] + bias_sm[3][jj];
            float r_ = sigm(rsum);
            float z_ = sigm(zsum);
            float n_ = tanhf(ni + r_ * nh);
            float hold = hprev[b * HH + j];
            float hn = (1.0f - z_) * n_ + z_ * hold;
            hn = fminf(CLIPV, fmaxf(-CLIPV, hn));
            hnext[b * HH + j] = hn;
            out[((size_t)b * TT + t) * HH + j] = hn;
            if (write_hlast && t == TT - 1)
                out[(size_t)BB * TT * HH + b * HH + j] = hn;
        }

        // --- grid barrier (128 co-resident blocks; 1 block/SM by smem) ---
        __syncthreads();
        if (tid == 0) {
            __threadfence();
            unsigned prev = atomicAdd(&g_arrive, 1u);
            unsigned target = (unsigned)(t + 1) * nblocks;
            if (prev + 1u == target) {
                atomicExch(&g_release, (unsigned)(t + 1));
            } else {
                while (*(volatile unsigned*)&g_release < (unsigned)(t + 1))
                    __nanosleep(32);
            }
            __threadfence();
        }
        __syncthreads();

        #undef STAGE_LOAD
        #undef STAGE_STORE
        #undef KLOOP
    }
}

__global__ void init_h(const float* __restrict__ h0) {
    int i = blockIdx.x * 256 + threadIdx.x;
    if (i < BB * HH) g_h[0][i] = h0[i & (HH - 1)];
    if (i == 0) { g_arrive = 0u; g_release = 0u; }
}

extern "C" void kernel_launch(void* const* d_in, const int* in_sizes, int n_in,
                              void* d_out, int out_size) {
    const float* x    = (const float*)d_in[0];
    const float* h0   = (const float*)d_in[1];
    const float* w_ih = (const float*)d_in[2];
    const float* w_hh = (const float*)d_in[3];
    const float* b_ih = (const float*)d_in[4];
    const float* b_hh = (const float*)d_in[5];
    float* out = (float*)d_out;

    cudaFuncSetAttribute(gru_persistent,
                         cudaFuncAttributeMaxDynamicSharedMemorySize, SMEM_BYTES);

    init_h<<<(BB * HH + 255) / 256, 256>>>(h0);

    const size_t main_elems = (size_t)BB * TT * HH;
    int write_hlast = ((size_t)out_size >= main_elems + (size_t)BB * HH) ? 1 : 0;

    dim3 grid(HH / JT, BB / MB);   // 32 x 4 = 128 blocks, 1 per SM
    gru_persistent<<<grid, 384, SMEM_BYTES>>>(x, w_ih, w_hh, b_ih, b_hh, out,
                                              write_hlast);
}